// round 7
// baseline (speedup 1.0000x reference)
#include <cuda_runtime.h>
#include <cuda_fp16.h>
#include <cstdint>

// LSTMDecoder on GB300 (sm_103 ptxas -> mma.sync path; tcgen05 unavailable).
// 48 sequential steps of z = h @ W^T + bias (M=2048, N=4096, K=1024),
// fused i/f/g/o gate epilogue.
// R7: 64x64 warp tiles (4 warps/CTA, 128 thr, 2x2 grid) to cut fragment
// crossbar traffic 96KB->64KB per k-tile; fp16 m16n8k16 + ldmatrix.x4,
// BK=64, 128x128 CTA tiles, 2 CTAs/SM, cp.async 3-stage pipeline,
// shfl-paired gate fusion, contiguous per-step output + final transpose.

#define HDIM   1024
#define NBATCH 2048
#define LSTEPS 48
#define TM     128          // CTA rows (batch)
#define TN     128          // CTA z-cols (= 32 j x 4 gates, interleaved j*4+g)
#define TJ     32
#define BK     64           // K per stage (64 fp16 = 128B rows)
#define NSTAGE 3
#define KTILES (HDIM / BK)  // 16
#define NTHR   128

#define SM_BIAS 0                                   // 128 floats
#define SM_PIPE 1024
#define A_BYTES (TM * BK * 2)                       // 16384
#define B_BYTES (TN * BK * 2)                       // 16384
#define STAGE_BYTES (A_BYTES + B_BYTES)             // 32768
#define SMEM_TOTAL (SM_PIPE + NSTAGE * STAGE_BYTES) // 99328 (2 CTAs/SM)

#define EPS 33                                      // epilogue j-stride (padded)

#define SWZ(o) ((o) ^ (((o) >> 3) & 0x70))

__device__ __half g_h[2][NBATCH * HDIM];         // fp16 h ping-pong
__device__ float  g_c[NBATCH * HDIM];            // cell state (fp32)
__device__ __half g_Wr[4 * HDIM * HDIM];         // reordered fp16 W: row j*4+g
__device__ float  g_biasr[4 * HDIM];             // reordered bias
__device__ float  g_hist[LSTEPS][NBATCH * HDIM]; // full-precision h history

// ---------- helpers ----------
__device__ __forceinline__ uint32_t smem_u32(const void* p) {
    uint32_t a;
    asm("{ .reg .u64 t; cvta.to.shared.u64 t, %1; cvt.u32.u64 %0, t; }" : "=r"(a) : "l"(p));
    return a;
}
__device__ __forceinline__ void cpa16(uint32_t dst, const void* src) {
    asm volatile("cp.async.cg.shared.global [%0], [%1], 16;" :: "r"(dst), "l"(src));
}
#define CP_COMMIT() asm volatile("cp.async.commit_group;" ::: "memory")
#define CP_WAIT1()  asm volatile("cp.async.wait_group 1;" ::: "memory")

__device__ __forceinline__ void ldm_x4(uint32_t* r, uint32_t addr) {
    asm volatile("ldmatrix.sync.aligned.m8n8.x4.shared.b16 {%0,%1,%2,%3}, [%4];"
                 : "=r"(r[0]), "=r"(r[1]), "=r"(r[2]), "=r"(r[3]) : "r"(addr));
}
__device__ __forceinline__ void mma16(float* c, const uint32_t* a, const uint32_t* b) {
    asm("mma.sync.aligned.m16n8k16.row.col.f32.f16.f16.f32 "
        "{%0,%1,%2,%3}, {%4,%5,%6,%7}, {%8,%9}, {%0,%1,%2,%3};"
        : "+f"(c[0]), "+f"(c[1]), "+f"(c[2]), "+f"(c[3])
        : "r"(a[0]), "r"(a[1]), "r"(a[2]), "r"(a[3]), "r"(b[0]), "r"(b[1]));
}
__device__ __forceinline__ float sigm(float x) {
    return __fdividef(1.0f, 1.0f + __expf(-x));
}
__device__ __forceinline__ float tanh_(float x) {
    return __fdividef(2.0f, 1.0f + __expf(-2.0f * x)) - 1.0f;
}

// ---------- prep kernels ----------
__global__ void prep_h(const float* __restrict__ h_in) {
    int i = blockIdx.x * 256 + threadIdx.x;     // float4 index
    float4 v = ((const float4*)h_in)[i];
    __half2 lo = __floats2half2_rn(v.x, v.y);
    __half2 hi = __floats2half2_rn(v.z, v.w);
    ((uint2*)g_h[0])[i] = make_uint2(*(uint32_t*)&lo, *(uint32_t*)&hi);
}
__global__ void prep_w(const float* __restrict__ W) {
    int idx = blockIdx.x * 256 + threadIdx.x;   // 4096 rows x 256 float4
    int rn = idx >> 8, k4 = idx & 255;
    int j = rn >> 2, g = rn & 3;
    float4 v = ((const float4*)W)[(size_t)(g * HDIM + j) * (HDIM / 4) + k4];
    __half2 lo = __floats2half2_rn(v.x, v.y);
    __half2 hi = __floats2half2_rn(v.z, v.w);
    ((uint2*)g_Wr)[(size_t)rn * (HDIM / 4) + k4] =
        make_uint2(*(uint32_t*)&lo, *(uint32_t*)&hi);
}
__global__ void prep_bias(const float* __restrict__ bi, const float* __restrict__ bh) {
    int i = blockIdx.x * 256 + threadIdx.x;
    if (i < 4 * HDIM) {
        int j = i >> 2, g = i & 3;
        g_biasr[i] = bi[g * HDIM + j] + bh[g * HDIM + j];
    }
}

// ---------- main step kernel ----------
__global__ __launch_bounds__(NTHR, 2)
void lstm_step(int t) {
    extern __shared__ char smc[];
    float* sbias = (float*)(smc + SM_BIAS);
    const uint32_t smb = smem_u32(smc);

    const int tid = threadIdx.x;
    const int w = tid >> 5, lane = tid & 31;
    const int gid = lane >> 2, tig = lane & 3;
    const int wm = w >> 1, wn = w & 1;          // 2 x 2 warp grid, 64x64 tiles
    const int m0 = blockIdx.x * TM;
    const int n0 = blockIdx.y * TN;
    const int jblk = blockIdx.y * TJ;

    const __half* __restrict__ hsrc = g_h[t & 1];
    __half* __restrict__ hdst = g_h[(t + 1) & 1];
    float* __restrict__ hist = g_hist[t];

    sbias[tid] = g_biasr[n0 + tid];

    auto load_tile = [&](int kt, int s) {
        const uint32_t abase = smb + SM_PIPE + s * STAGE_BYTES;
        const uint32_t bbase = abase + A_BYTES;
        const __half* asrc = hsrc + (size_t)m0 * HDIM + kt * BK;
        const __half* bsrc = g_Wr + (size_t)n0 * HDIM + kt * BK;
#pragma unroll
        for (int p = 0; p < 8; p++) {           // A: 128 rows x 128B
            int idx = tid + p * NTHR;
            int row = idx >> 3, ch = idx & 7;
            uint32_t off = (uint32_t)(row * 128 + ch * 16);
            cpa16(abase + SWZ(off), asrc + (size_t)row * HDIM + ch * 8);
        }
#pragma unroll
        for (int p = 0; p < 8; p++) {           // B: 128 rows x 128B
            int idx = tid + p * NTHR;
            int row = idx >> 3, ch = idx & 7;
            uint32_t off = (uint32_t)(row * 128 + ch * 16);
            cpa16(bbase + SWZ(off), bsrc + (size_t)row * HDIM + ch * 8);
        }
    };

    load_tile(0, 0); CP_COMMIT();
    load_tile(1, 1); CP_COMMIT();
    __syncthreads();  // sbias visible

    // accumulators, bias folded in (cols of c0/c2 = base, c1/c3 = base+1)
    float acc[4][8][4];
#pragma unroll
    for (int mf = 0; mf < 4; mf++)
#pragma unroll
        for (int nf = 0; nf < 8; nf++) {
            int c = wn * 64 + nf * 8 + 2 * tig;
            float b0 = sbias[c], b1 = sbias[c + 1];
            acc[mf][nf][0] = b0; acc[mf][nf][1] = b1;
            acc[mf][nf][2] = b0; acc[mf][nf][3] = b1;
        }

    // ---- ldmatrix lane addressing (relative to stage base) ----
    // addr(kk) = (stage_base + rel0) ^ (kk << 5)  [swizzle bits 4-6, carry-free]
    const int rit = lane & 7;          // row-within-8
    const int tg  = lane >> 3;         // ldmatrix tile group 0..3
    // A per mf: tiles [m0-7 klo, m8-15 klo, m0-7 khi, m8-15 khi]
    uint32_t ra[4];
#pragma unroll
    for (int mf = 0; mf < 4; mf++) {
        int arow = wm * 64 + mf * 16 + (tg & 1) * 8 + rit;
        ra[mf] = SM_PIPE + (uint32_t)arow * 128 + ((uint32_t)((tg >> 1) ^ rit) << 4);
    }
    // B per pair p (covers nf=2p,2p+1): [n(2p) klo, n(2p) khi, n(2p+1) klo, n(2p+1) khi]
    uint32_t rb[4];
#pragma unroll
    for (int p = 0; p < 4; p++) {
        int brow = wn * 64 + (2 * p + (tg >> 1)) * 8 + rit;
        rb[p] = SM_PIPE + A_BYTES + (uint32_t)brow * 128 +
                ((uint32_t)((tg & 1) ^ rit) << 4);
    }

#pragma unroll 1
    for (int kt = 0; kt < KTILES; kt++) {
        const int s = kt % NSTAGE;
        CP_WAIT1();
        __syncthreads();
        if (kt + 2 < KTILES) load_tile(kt + 2, (kt + 2) % NSTAGE);
        CP_COMMIT();

        const uint32_t sb = smb + (uint32_t)s * STAGE_BYTES;
        uint32_t a0 = sb + ra[0], a1 = sb + ra[1], a2 = sb + ra[2], a3 = sb + ra[3];
        uint32_t b0 = sb + rb[0], b1 = sb + rb[1], b2 = sb + rb[2], b3 = sb + rb[3];
#pragma unroll
        for (int kk = 0; kk < 4; kk++) {        // 4 x k16 = 64 K elems
            const uint32_t x = (uint32_t)kk << 5;
            uint32_t af[4][4], bf[4][4];        // bf[p] = {n2p:lo,hi, n2p+1:lo,hi}
            ldm_x4(af[0], a0 ^ x);
            ldm_x4(af[1], a1 ^ x);
            ldm_x4(af[2], a2 ^ x);
            ldm_x4(af[3], a3 ^ x);
            ldm_x4(bf[0], b0 ^ x);
            ldm_x4(bf[1], b1 ^ x);
            ldm_x4(bf[2], b2 ^ x);
            ldm_x4(bf[3], b3 ^ x);
#pragma unroll
            for (int mf = 0; mf < 4; mf++)
#pragma unroll
                for (int nf = 0; nf < 8; nf++)
                    mma16(acc[mf][nf], af[mf], &bf[nf >> 1][(nf & 1) * 2]);
        }
    }
    __syncthreads();  // all MMAs done before smem reuse

    // ---- epilogue: shfl-pair gate fusion -> smem staging ----
    float* P  = (float*)(smc + SM_PIPE);           // i*g
    float* F  = P + TM * EPS;                      // f
    float* OG = F + TM * EPS;                      // o
    const int odd = tig & 1;

#pragma unroll
    for (int mf = 0; mf < 4; mf++)
#pragma unroll
        for (int nf = 0; nf < 8; nf++) {
            float c0 = acc[mf][nf][0], c1 = acc[mf][nf][1];
            float c2 = acc[mf][nf][2], c3 = acc[mf][nf][3];
            float e0 = __shfl_xor_sync(0xFFFFFFFFu, c0, 1);
            float e1 = __shfl_xor_sync(0xFFFFFFFFu, c1, 1);
            float e2 = __shfl_xor_sync(0xFFFFFFFFu, c2, 1);
            float e3 = __shfl_xor_sync(0xFFFFFFFFu, c3, 1);
            // even lane: row gid,   gates i,f own (c0,c1), g,o from odd (e0,e1)
            // odd lane:  row gid+8, gates g,o own (c2,c3), i,f from even (e2,e3)
            float zi = odd ? e2 : c0;
            float zf = odd ? e3 : c1;
            float zg = odd ? c2 : e0;
            float zo = odd ? c3 : e1;
            int row = wm * 64 + mf * 16 + gid + (odd ? 8 : 0);
            int jl  = wn * 16 + nf * 2 + (tig >> 1);
            float ig = sigm(zi), fg = sigm(zf), gg = tanh_(zg), og = sigm(zo);
            P[row * EPS + jl]  = ig * gg;
            F[row * EPS + jl]  = fg;
            OG[row * EPS + jl] = og;
        }
    __syncthreads();

    // ---- coalesced state update ----
    const bool first = (t == 0);
#pragma unroll
    for (int it = 0; it < (TM * TJ) / NTHR; it++) {
        int idx = it * NTHR + tid;     // 128 rows x 32 j
        int row = idx >> 5, j = idx & 31;
        size_t g = (size_t)(m0 + row) * HDIM + jblk + j;
        float cold = first ? 0.0f : g_c[g];
        float cnew = F[row * EPS + j] * cold + P[row * EPS + j];
        float h = OG[row * EPS + j] * tanh_(cnew);
        g_c[g]  = cnew;
        hist[g] = h;                    // full precision for output
        hdst[g] = __float2half_rn(h);   // fp16 for next GEMM
    }
}

// ---------- final transpose: g_hist[t][n*H+j] -> out[(n*H+j)*L + t] ----------
__global__ void finalize(float* __restrict__ out) {
    const int p = blockIdx.x * 256 + threadIdx.x;
    float v[LSTEPS];
#pragma unroll
    for (int t = 0; t < LSTEPS; t++) v[t] = g_hist[t][p];
    float4* o = (float4*)(out + (size_t)p * LSTEPS);
#pragma unroll
    for (int q = 0; q < LSTEPS / 4; q++)
        o[q] = make_float4(v[4 * q], v[4 * q + 1], v[4 * q + 2], v[4 * q + 3]);
}

extern "C" void kernel_launch(void* const* d_in, const int* in_sizes, int n_in,
                              void* d_out, int out_size) {
    const float* h_in = (const float*)d_in[0];
    const float* W    = (const float*)d_in[1];
    const float* b_ih = (const float*)d_in[2];
    const float* b_hh = (const float*)d_in[3];

    cudaFuncSetAttribute(lstm_step, cudaFuncAttributeMaxDynamicSharedMemorySize, SMEM_TOTAL);

    prep_h<<<NBATCH * HDIM / 4 / 256, 256>>>(h_in);
    prep_w<<<4 * HDIM * HDIM / 4 / 256, 256>>>(W);
    prep_bias<<<16, 256>>>(b_ih, b_hh);

    for (int t = 0; t < LSTEPS; t++) {
        lstm_step<<<dim3(NBATCH / TM, 4 * HDIM / TN), NTHR, SMEM_TOTAL>>>(t);
    }
    finalize<<<NBATCH * HDIM / 256, 256>>>((float*)d_out);
}

// round 8
// speedup vs baseline: 1.0504x; 1.0504x over previous
#include <cuda_runtime.h>
#include <cuda_fp16.h>
#include <cstdint>

// LSTMDecoder on GB300 (sm_103 ptxas -> mma.sync path; tcgen05 unavailable).
// 48 sequential steps of z = h @ W^T + bias (M=2048, N=4096, K=1024),
// fused i/f/g/o gate epilogue.
// R8: register-level fragment software pipeline (A double-buffered, B pair-
// streamed) so LDSM never sits on the MMA critical path; tile-boundary
// barrier placed after all current-tile LDSMs (race-free stage reuse).
// fp16 m16n8k16 + ldmatrix.x4, BK=64, 128x128 CTA tiles, 64x64 warp tiles,
// 2 CTAs/SM, cp.async 3-stage pipeline, shfl-paired gate fusion,
// contiguous per-step output + final transpose.

#define HDIM   1024
#define NBATCH 2048
#define LSTEPS 48
#define TM     128          // CTA rows (batch)
#define TN     128          // CTA z-cols (= 32 j x 4 gates, interleaved j*4+g)
#define TJ     32
#define BK     64           // K per stage (64 fp16 = 128B rows)
#define NSTAGE 3
#define KTILES (HDIM / BK)  // 16
#define NTHR   128

#define SM_BIAS 0                                   // 128 floats
#define SM_PIPE 1024
#define A_BYTES (TM * BK * 2)                       // 16384
#define B_BYTES (TN * BK * 2)                       // 16384
#define STAGE_BYTES (A_BYTES + B_BYTES)             // 32768
#define SMEM_TOTAL (SM_PIPE + NSTAGE * STAGE_BYTES) // 99328 (2 CTAs/SM)

#define EPS 33                                      // epilogue j-stride (padded)

#define SWZ(o) ((o) ^ (((o) >> 3) & 0x70))

__device__ __half g_h[2][NBATCH * HDIM];         // fp16 h ping-pong
__device__ float  g_c[NBATCH * HDIM];            // cell state (fp32)
__device__ __half g_Wr[4 * HDIM * HDIM];         // reordered fp16 W: row j*4+g
__device__ float  g_biasr[4 * HDIM];             // reordered bias
__device__ float  g_hist[LSTEPS][NBATCH * HDIM]; // full-precision h history

// ---------- helpers ----------
__device__ __forceinline__ uint32_t smem_u32(const void* p) {
    uint32_t a;
    asm("{ .reg .u64 t; cvta.to.shared.u64 t, %1; cvt.u32.u64 %0, t; }" : "=r"(a) : "l"(p));
    return a;
}
__device__ __forceinline__ void cpa16(uint32_t dst, const void* src) {
    asm volatile("cp.async.cg.shared.global [%0], [%1], 16;" :: "r"(dst), "l"(src));
}
#define CP_COMMIT() asm volatile("cp.async.commit_group;" ::: "memory")
#define CP_WAIT(n)  asm volatile("cp.async.wait_group %0;" :: "n"(n) : "memory")

__device__ __forceinline__ void ldm_x4(uint32_t* r, uint32_t addr) {
    asm volatile("ldmatrix.sync.aligned.m8n8.x4.shared.b16 {%0,%1,%2,%3}, [%4];"
                 : "=r"(r[0]), "=r"(r[1]), "=r"(r[2]), "=r"(r[3]) : "r"(addr));
}
__device__ __forceinline__ void mma16(float* c, const uint32_t* a, const uint32_t* b) {
    asm("mma.sync.aligned.m16n8k16.row.col.f32.f16.f16.f32 "
        "{%0,%1,%2,%3}, {%4,%5,%6,%7}, {%8,%9}, {%0,%1,%2,%3};"
        : "+f"(c[0]), "+f"(c[1]), "+f"(c[2]), "+f"(c[3])
        : "r"(a[0]), "r"(a[1]), "r"(a[2]), "r"(a[3]), "r"(b[0]), "r"(b[1]));
}
__device__ __forceinline__ float sigm(float x) {
    return __fdividef(1.0f, 1.0f + __expf(-x));
}
__device__ __forceinline__ float tanh_(float x) {
    return __fdividef(2.0f, 1.0f + __expf(-2.0f * x)) - 1.0f;
}

// ---------- prep kernels ----------
__global__ void prep_h(const float* __restrict__ h_in) {
    int i = blockIdx.x * 256 + threadIdx.x;     // float4 index
    float4 v = ((const float4*)h_in)[i];
    __half2 lo = __floats2half2_rn(v.x, v.y);
    __half2 hi = __floats2half2_rn(v.z, v.w);
    ((uint2*)g_h[0])[i] = make_uint2(*(uint32_t*)&lo, *(uint32_t*)&hi);
}
__global__ void prep_w(const float* __restrict__ W) {
    int idx = blockIdx.x * 256 + threadIdx.x;   // 4096 rows x 256 float4
    int rn = idx >> 8, k4 = idx & 255;
    int j = rn >> 2, g = rn & 3;
    float4 v = ((const float4*)W)[(size_t)(g * HDIM + j) * (HDIM / 4) + k4];
    __half2 lo = __floats2half2_rn(v.x, v.y);
    __half2 hi = __floats2half2_rn(v.z, v.w);
    ((uint2*)g_Wr)[(size_t)rn * (HDIM / 4) + k4] =
        make_uint2(*(uint32_t*)&lo, *(uint32_t*)&hi);
}
__global__ void prep_bias(const float* __restrict__ bi, const float* __restrict__ bh) {
    int i = blockIdx.x * 256 + threadIdx.x;
    if (i < 4 * HDIM) {
        int j = i >> 2, g = i & 3;
        g_biasr[i] = bi[g * HDIM + j] + bh[g * HDIM + j];
    }
}

// ---------- main step kernel ----------
__global__ __launch_bounds__(NTHR, 2)
void lstm_step(int t) {
    extern __shared__ char smc[];
    float* sbias = (float*)(smc + SM_BIAS);
    const uint32_t smb = smem_u32(smc);

    const int tid = threadIdx.x;
    const int w = tid >> 5, lane = tid & 31;
    const int gid = lane >> 2, tig = lane & 3;
    const int wm = w >> 1, wn = w & 1;          // 2 x 2 warp grid, 64x64 tiles
    const int m0 = blockIdx.x * TM;
    const int n0 = blockIdx.y * TN;
    const int jblk = blockIdx.y * TJ;

    const __half* __restrict__ hsrc = g_h[t & 1];
    __half* __restrict__ hdst = g_h[(t + 1) & 1];
    float* __restrict__ hist = g_hist[t];

    sbias[tid] = g_biasr[n0 + tid];

    auto load_tile = [&](int kt, int s) {
        const uint32_t abase = smb + SM_PIPE + s * STAGE_BYTES;
        const uint32_t bbase = abase + A_BYTES;
        const __half* asrc = hsrc + (size_t)m0 * HDIM + kt * BK;
        const __half* bsrc = g_Wr + (size_t)n0 * HDIM + kt * BK;
#pragma unroll
        for (int p = 0; p < 8; p++) {           // A: 128 rows x 128B
            int idx = tid + p * NTHR;
            int row = idx >> 3, ch = idx & 7;
            uint32_t off = (uint32_t)(row * 128 + ch * 16);
            cpa16(abase + SWZ(off), asrc + (size_t)row * HDIM + ch * 8);
        }
#pragma unroll
        for (int p = 0; p < 8; p++) {           // B: 128 rows x 128B
            int idx = tid + p * NTHR;
            int row = idx >> 3, ch = idx & 7;
            uint32_t off = (uint32_t)(row * 128 + ch * 16);
            cpa16(bbase + SWZ(off), bsrc + (size_t)row * HDIM + ch * 8);
        }
    };

    // ---- ldmatrix lane addressing (relative to stage base) ----
    // addr(kk) = (stage_base + rel) ^ (kk << 5)  [swizzle bits 4-6, carry-free]
    const int rit = lane & 7;          // row-within-8
    const int tg  = lane >> 3;         // ldmatrix tile group 0..3
    uint32_t ra[4];                    // A per mf: [m0-7 klo, m8-15 klo, m0-7 khi, m8-15 khi]
#pragma unroll
    for (int mf = 0; mf < 4; mf++) {
        int arow = wm * 64 + mf * 16 + (tg & 1) * 8 + rit;
        ra[mf] = SM_PIPE + (uint32_t)arow * 128 + ((uint32_t)((tg >> 1) ^ rit) << 4);
    }
    uint32_t rb[4];                    // B pair p: [n2p klo, n2p khi, n2p+1 klo, n2p+1 khi]
#pragma unroll
    for (int p = 0; p < 4; p++) {
        int brow = wn * 64 + (2 * p + (tg >> 1)) * 8 + rit;
        rb[p] = SM_PIPE + A_BYTES + (uint32_t)brow * 128 +
                ((uint32_t)((tg & 1) ^ rit) << 4);
    }

    // prologue: 3 stages in flight
    load_tile(0, 0); CP_COMMIT();
    load_tile(1, 1); CP_COMMIT();
    load_tile(2, 2); CP_COMMIT();

    // accumulators, bias folded in (cols of c0/c2 = base, c1/c3 = base+1)
    float acc[4][8][4];
#pragma unroll
    for (int mf = 0; mf < 4; mf++)
#pragma unroll
        for (int nf = 0; nf < 8; nf++) {
            int c = wn * 64 + nf * 8 + 2 * tig;
            float b0 = sbias[c], b1 = sbias[c + 1];
            acc[mf][nf][0] = b0; acc[mf][nf][1] = b1;
            acc[mf][nf][2] = b0; acc[mf][nf][3] = b1;
        }

    CP_WAIT(2);           // tile 0 resident
    __syncthreads();

    // fragment buffers: A double (per kk), B pair-streamed double
    uint32_t af[2][4][4];
    uint32_t bp[2][4];
    ldm_x4(af[0][0], smb + ra[0]);    // A(tile0, kk0)
    ldm_x4(af[0][1], smb + ra[1]);
    ldm_x4(af[0][2], smb + ra[2]);
    ldm_x4(af[0][3], smb + ra[3]);
    ldm_x4(bp[0], smb + rb[0]);       // B(tile0, kk0, pair0)

#pragma unroll 1
    for (int kt = 0; kt < KTILES; kt++) {
        const int s  = kt % NSTAGE;
        const int sn = (kt + 1) % NSTAGE;
        const uint32_t sb  = smb + (uint32_t)s  * STAGE_BYTES;
        const uint32_t sbn = smb + (uint32_t)sn * STAGE_BYTES;
        const bool lastTile = (kt == KTILES - 1);

#pragma unroll
        for (int kk = 0; kk < 4; kk++) {
            const int ab = kk & 1;
            const uint32_t xc = (uint32_t)kk << 5;
            const uint32_t xn = (uint32_t)(kk + 1) << 5;   // only used when kk<3
#pragma unroll
            for (int p = 0; p < 4; p++) {
                const int pb = p & 1;
                // ---- issue future loads (never on this MMA block's path) ----
                if (p == 0) {
                    ldm_x4(bp[pb ^ 1], (sb + rb[1]) ^ xc);
                } else if (p == 1) {
                    ldm_x4(bp[pb ^ 1], (sb + rb[2]) ^ xc);
                } else if (p == 2) {
                    ldm_x4(bp[pb ^ 1], (sb + rb[3]) ^ xc);   // pair3, current tile
                    if (kk < 3) {                            // A(kk+1), same tile
                        ldm_x4(af[ab ^ 1][0], (sb + ra[0]) ^ xn);
                        ldm_x4(af[ab ^ 1][1], (sb + ra[1]) ^ xn);
                        ldm_x4(af[ab ^ 1][2], (sb + ra[2]) ^ xn);
                        ldm_x4(af[ab ^ 1][3], (sb + ra[3]) ^ xn);
                    }
                } else { // p == 3
                    if (kk < 3) {
                        ldm_x4(bp[pb ^ 1], (sb + rb[0]) ^ xn);   // pair0 of next kk
                    } else if (!lastTile) {
                        // all current-tile LDSMs issued -> safe to sync + reuse stage
                        if (kt < KTILES - 2) { CP_WAIT(1); } else { CP_WAIT(0); }
                        __syncthreads();
                        ldm_x4(af[ab ^ 1][0], sbn + ra[0]);      // A(kt+1, kk0)
                        ldm_x4(af[ab ^ 1][1], sbn + ra[1]);
                        ldm_x4(af[ab ^ 1][2], sbn + ra[2]);
                        ldm_x4(af[ab ^ 1][3], sbn + ra[3]);
                        ldm_x4(bp[pb ^ 1], sbn + rb[0]);         // pair0 (kt+1, kk0)
                        if (kt + 3 < KTILES) {                   // refill freed stage
                            load_tile(kt + 3, s);
                            CP_COMMIT();
                        }
                    }
                }
                // ---- 8 MMAs with current pair p (register-resident) ----
#pragma unroll
                for (int mf = 0; mf < 4; mf++) {
                    mma16(acc[mf][2 * p],     af[ab][mf], &bp[pb][0]);
                    mma16(acc[mf][2 * p + 1], af[ab][mf], &bp[pb][2]);
                }
            }
        }
    }
    __syncthreads();  // all MMAs done before smem reuse

    // ---- epilogue: shfl-pair gate fusion -> smem staging ----
    float* P  = (float*)(smc + SM_PIPE);           // i*g
    float* F  = P + TM * EPS;                      // f
    float* OG = F + TM * EPS;                      // o
    const int odd = tig & 1;

#pragma unroll
    for (int mf = 0; mf < 4; mf++)
#pragma unroll
        for (int nf = 0; nf < 8; nf++) {
            float c0 = acc[mf][nf][0], c1 = acc[mf][nf][1];
            float c2 = acc[mf][nf][2], c3 = acc[mf][nf][3];
            float e0 = __shfl_xor_sync(0xFFFFFFFFu, c0, 1);
            float e1 = __shfl_xor_sync(0xFFFFFFFFu, c1, 1);
            float e2 = __shfl_xor_sync(0xFFFFFFFFu, c2, 1);
            float e3 = __shfl_xor_sync(0xFFFFFFFFu, c3, 1);
            // even lane: row gid,   gates i,f own (c0,c1), g,o from odd (e0,e1)
            // odd lane:  row gid+8, gates g,o own (c2,c3), i,f from even (e2,e3)
            float zi = odd ? e2 : c0;
            float zf = odd ? e3 : c1;
            float zg = odd ? c2 : e0;
            float zo = odd ? c3 : e1;
            int row = wm * 64 + mf * 16 + gid + (odd ? 8 : 0);
            int jl  = wn * 16 + nf * 2 + (tig >> 1);
            float ig = sigm(zi), fg = sigm(zf), gg = tanh_(zg), og = sigm(zo);
            P[row * EPS + jl]  = ig * gg;
            F[row * EPS + jl]  = fg;
            OG[row * EPS + jl] = og;
        }
    __syncthreads();

    // ---- coalesced state update ----
    const bool first = (t == 0);
#pragma unroll
    for (int it = 0; it < (TM * TJ) / NTHR; it++) {
        int idx = it * NTHR + tid;     // 128 rows x 32 j
        int row = idx >> 5, j = idx & 31;
        size_t g = (size_t)(m0 + row) * HDIM + jblk + j;
        float cold = first ? 0.0f : g_c[g];
        float cnew = F[row * EPS + j] * cold + P[row * EPS + j];
        float h = OG[row * EPS + j] * tanh_(cnew);
        g_c[g]  = cnew;
        hist[g] = h;                    // full precision for output
        hdst[g] = __float2half_rn(h);   // fp16 for next GEMM
    }
}

// ---------- final transpose: g_hist[t][n*H+j] -> out[(n*H+j)*L + t] ----------
__global__ void finalize(float* __restrict__ out) {
    const int p = blockIdx.x * 256 + threadIdx.x;
    float v[LSTEPS];
#pragma unroll
    for (int t = 0; t < LSTEPS; t++) v[t] = g_hist[t][p];
    float4* o = (float4*)(out + (size_t)p * LSTEPS);
#pragma unroll
    for (int q = 0; q < LSTEPS / 4; q++)
        o[q] = make_float4(v[4 * q], v[4 * q + 1], v[4 * q + 2], v[4 * q + 3]);
}

extern "C" void kernel_launch(void* const* d_in, const int* in_sizes, int n_in,
                              void* d_out, int out_size) {
    const float* h_in = (const float*)d_in[0];
    const float* W    = (const float*)d_in[1];
    const float* b_ih = (const float*)d_in[2];
    const float* b_hh = (const float*)d_in[3];

    cudaFuncSetAttribute(lstm_step, cudaFuncAttributeMaxDynamicSharedMemorySize, SMEM_TOTAL);

    prep_h<<<NBATCH * HDIM / 4 / 256, 256>>>(h_in);
    prep_w<<<4 * HDIM * HDIM / 4 / 256, 256>>>(W);
    prep_bias<<<16, 256>>>(b_ih, b_hh);

    for (int t = 0; t < LSTEPS; t++) {
        lstm_step<<<dim3(NBATCH / TM, 4 * HDIM / TN), NTHR, SMEM_TOTAL>>>(t);
    }
    finalize<<<NBATCH * HDIM / 256, 256>>>((float*)d_out);
}

// round 9
// speedup vs baseline: 1.1139x; 1.0605x over previous
#include <cuda_runtime.h>
#include <cuda_fp16.h>
#include <cstdint>

// LSTMDecoder on GB300 (sm_103 ptxas -> mma.sync path; tcgen05 unavailable).
// 48 sequential steps of z = h @ W^T + bias (M=2048, N=4096, K=1024),
// fused i/f/g/o gate epilogue.
// R9: barrier-free mainloop. mbarrier producer/consumer pipeline
// (cp.async.mbarrier.arrive.noinc full-barriers, per-warp empty-barriers)
// lets the 16 warps/SM free-run with <=3-tile skew, so the tensor pipe is
// fed through every k-tile boundary. Config = R6 (fp16 m16n8k16 +
// ldmatrix.x4, BK=64, 128x128 CTA tile, 32x64 warp tiles, 2 CTAs/SM).

#define HDIM   1024
#define NBATCH 2048
#define LSTEPS 48
#define TM     128          // CTA rows (batch)
#define TN     128          // CTA z-cols (= 32 j x 4 gates, interleaved j*4+g)
#define TJ     32
#define BK     64           // K per stage (64 fp16 = 128B rows)
#define NSTAGE 3
#define KTILES (HDIM / BK)  // 16
#define NTHR   256

#define SM_BIAS 0                                   // 128 floats = 512B
#define SM_MBAR 512                                 // full[s]@512+16s, empty[s]@520+16s
#define SM_PIPE 1024
#define A_BYTES (TM * BK * 2)                       // 16384
#define B_BYTES (TN * BK * 2)                       // 16384
#define STAGE_BYTES (A_BYTES + B_BYTES)             // 32768
#define SMEM_TOTAL (SM_PIPE + NSTAGE * STAGE_BYTES) // 99328 (2 CTAs/SM)

#define EPS 33                                      // epilogue j-stride (padded)

#define SWZ(o) ((o) ^ (((o) >> 3) & 0x70))

__device__ __half g_h[2][NBATCH * HDIM];         // fp16 h ping-pong
__device__ float  g_c[NBATCH * HDIM];            // cell state (fp32)
__device__ __half g_Wr[4 * HDIM * HDIM];         // reordered fp16 W: row j*4+g
__device__ float  g_biasr[4 * HDIM];             // reordered bias
__device__ float  g_hist[LSTEPS][NBATCH * HDIM]; // full-precision h history

// ---------- helpers ----------
__device__ __forceinline__ uint32_t smem_u32(const void* p) {
    uint32_t a;
    asm("{ .reg .u64 t; cvta.to.shared.u64 t, %1; cvt.u32.u64 %0, t; }" : "=r"(a) : "l"(p));
    return a;
}
__device__ __forceinline__ void cpa16(uint32_t dst, const void* src) {
    asm volatile("cp.async.cg.shared.global [%0], [%1], 16;" :: "r"(dst), "l"(src));
}
__device__ __forceinline__ void mbar_init(uint32_t b, uint32_t cnt) {
    asm volatile("mbarrier.init.shared.b64 [%0], %1;" :: "r"(b), "r"(cnt) : "memory");
}
__device__ __forceinline__ void mbar_arrive(uint32_t b) {
    asm volatile("mbarrier.arrive.shared.b64 _, [%0];" :: "r"(b) : "memory");
}
__device__ __forceinline__ void cpa_arrive(uint32_t b) {
    asm volatile("cp.async.mbarrier.arrive.noinc.shared.b64 [%0];" :: "r"(b) : "memory");
}
__device__ __forceinline__ void mbar_wait(uint32_t b, uint32_t parity) {
    uint32_t done = 0;
    while (!done) {
        asm volatile(
            "{ .reg .pred p;\n\t"
            "mbarrier.try_wait.parity.shared.b64 p, [%1], %2;\n\t"
            "selp.b32 %0, 1, 0, p; }"
            : "=r"(done) : "r"(b), "r"(parity) : "memory");
    }
}
__device__ __forceinline__ void ldm_x4(uint32_t* r, uint32_t addr) {
    asm volatile("ldmatrix.sync.aligned.m8n8.x4.shared.b16 {%0,%1,%2,%3}, [%4];"
                 : "=r"(r[0]), "=r"(r[1]), "=r"(r[2]), "=r"(r[3]) : "r"(addr));
}
__device__ __forceinline__ void mma16(float* c, const uint32_t* a, const uint32_t* b) {
    asm("mma.sync.aligned.m16n8k16.row.col.f32.f16.f16.f32 "
        "{%0,%1,%2,%3}, {%4,%5,%6,%7}, {%8,%9}, {%0,%1,%2,%3};"
        : "+f"(c[0]), "+f"(c[1]), "+f"(c[2]), "+f"(c[3])
        : "r"(a[0]), "r"(a[1]), "r"(a[2]), "r"(a[3]), "r"(b[0]), "r"(b[1]));
}
__device__ __forceinline__ float sigm(float x) {
    return __fdividef(1.0f, 1.0f + __expf(-x));
}
__device__ __forceinline__ float tanh_(float x) {
    return __fdividef(2.0f, 1.0f + __expf(-2.0f * x)) - 1.0f;
}

// ---------- prep kernels ----------
__global__ void prep_h(const float* __restrict__ h_in) {
    int i = blockIdx.x * 256 + threadIdx.x;     // float4 index
    float4 v = ((const float4*)h_in)[i];
    __half2 lo = __floats2half2_rn(v.x, v.y);
    __half2 hi = __floats2half2_rn(v.z, v.w);
    ((uint2*)g_h[0])[i] = make_uint2(*(uint32_t*)&lo, *(uint32_t*)&hi);
}
__global__ void prep_w(const float* __restrict__ W) {
    int idx = blockIdx.x * 256 + threadIdx.x;   // 4096 rows x 256 float4
    int rn = idx >> 8, k4 = idx & 255;
    int j = rn >> 2, g = rn & 3;
    float4 v = ((const float4*)W)[(size_t)(g * HDIM + j) * (HDIM / 4) + k4];
    __half2 lo = __floats2half2_rn(v.x, v.y);
    __half2 hi = __floats2half2_rn(v.z, v.w);
    ((uint2*)g_Wr)[(size_t)rn * (HDIM / 4) + k4] =
        make_uint2(*(uint32_t*)&lo, *(uint32_t*)&hi);
}
__global__ void prep_bias(const float* __restrict__ bi, const float* __restrict__ bh) {
    int i = blockIdx.x * 256 + threadIdx.x;
    if (i < 4 * HDIM) {
        int j = i >> 2, g = i & 3;
        g_biasr[i] = bi[g * HDIM + j] + bh[g * HDIM + j];
    }
}

// ---------- main step kernel ----------
__global__ __launch_bounds__(NTHR, 2)
void lstm_step(int t) {
    extern __shared__ char smc[];
    float* sbias = (float*)(smc + SM_BIAS);
    const uint32_t smb = smem_u32(smc);

    const int tid = threadIdx.x;
    const int w = tid >> 5, lane = tid & 31;
    const int gid = lane >> 2, tig = lane & 3;
    const int wm = w & 3, wn = w >> 2;          // 4 x 2 warp grid, 32x64 tiles
    const int m0 = blockIdx.x * TM;
    const int n0 = blockIdx.y * TN;
    const int jblk = blockIdx.y * TJ;

    const __half* __restrict__ hsrc = g_h[t & 1];
    __half* __restrict__ hdst = g_h[(t + 1) & 1];
    float* __restrict__ hist = g_hist[t];

    if (tid < TN) sbias[tid] = g_biasr[n0 + tid];
    if (tid == 0) {
#pragma unroll
        for (int s = 0; s < NSTAGE; s++) {
            mbar_init(smb + SM_MBAR + 16 * s, NTHR);     // full[s]: 256 async arrives
            mbar_init(smb + SM_MBAR + 16 * s + 8, 8);    // empty[s]: 8 warp arrives
        }
    }
    __syncthreads();   // bias + barrier init visible

    auto load_tile = [&](int kt, int s) {
        const uint32_t abase = smb + SM_PIPE + s * STAGE_BYTES;
        const uint32_t bbase = abase + A_BYTES;
        const __half* asrc = hsrc + (size_t)m0 * HDIM + kt * BK;
        const __half* bsrc = g_Wr + (size_t)n0 * HDIM + kt * BK;
#pragma unroll
        for (int p = 0; p < 4; p++) {           // A: 128 rows x 128B
            int idx = tid + p * NTHR;
            int row = idx >> 3, ch = idx & 7;
            uint32_t off = (uint32_t)(row * 128 + ch * 16);
            cpa16(abase + SWZ(off), asrc + (size_t)row * HDIM + ch * 8);
        }
#pragma unroll
        for (int p = 0; p < 4; p++) {           // B: 128 rows x 128B
            int idx = tid + p * NTHR;
            int row = idx >> 3, ch = idx & 7;
            uint32_t off = (uint32_t)(row * 128 + ch * 16);
            cpa16(bbase + SWZ(off), bsrc + (size_t)row * HDIM + ch * 8);
        }
    };

    // prologue: produce tiles 0..2 (stages fresh, no empty wait)
#pragma unroll
    for (int p = 0; p < NSTAGE; p++) {
        load_tile(p, p);
        cpa_arrive(smb + SM_MBAR + 16 * p);
    }

    // accumulators, bias folded in (cols of c0/c2 = base, c1/c3 = base+1)
    float acc[2][8][4];
#pragma unroll
    for (int mf = 0; mf < 2; mf++)
#pragma unroll
        for (int nf = 0; nf < 8; nf++) {
            int c = wn * 64 + nf * 8 + 2 * tig;
            float b0 = sbias[c], b1 = sbias[c + 1];
            acc[mf][nf][0] = b0; acc[mf][nf][1] = b1;
            acc[mf][nf][2] = b0; acc[mf][nf][3] = b1;
        }

    // ---- ldmatrix lane addressing (relative to stage base) ----
    // addr(kk) = (stage_base + rel) ^ (kk << 5) [swizzle bits 4-6, carry-free]
    const int rit = lane & 7;          // row-within-8
    const int tg  = lane >> 3;         // ldmatrix tile group 0..3
    uint32_t ra[2];                    // A per mf: [m0-7 klo, m8-15 klo, m0-7 khi, m8-15 khi]
#pragma unroll
    for (int mf = 0; mf < 2; mf++) {
        int arow = wm * 32 + mf * 16 + (tg & 1) * 8 + rit;
        ra[mf] = SM_PIPE + (uint32_t)arow * 128 + ((uint32_t)((tg >> 1) ^ rit) << 4);
    }
    uint32_t rb[4];                    // B pair p: [n2p klo, n2p khi, n2p+1 klo, n2p+1 khi]
#pragma unroll
    for (int p = 0; p < 4; p++) {
        int brow = wn * 64 + (2 * p + (tg >> 1)) * 8 + rit;
        rb[p] = SM_PIPE + A_BYTES + (uint32_t)brow * 128 +
                ((uint32_t)((tg & 1) ^ rit) << 4);
    }

#pragma unroll 1
    for (int kt = 0; kt < KTILES; kt++) {
        const int s = kt % NSTAGE;
        const uint32_t ph = (uint32_t)((kt / NSTAGE) & 1);
        const uint32_t fullb  = smb + SM_MBAR + 16 * s;
        const uint32_t emptyb = fullb + 8;

        mbar_wait(fullb, ph);   // tile kt resident (acquire)

        const uint32_t sb = smb + (uint32_t)s * STAGE_BYTES;
        const uint32_t a0 = sb + ra[0], a1 = sb + ra[1];
        const uint32_t b0 = sb + rb[0], b1 = sb + rb[1];
        const uint32_t b2 = sb + rb[2], b3 = sb + rb[3];
#pragma unroll
        for (int kk = 0; kk < 4; kk++) {        // 4 x k16 = 64 K elems
            const uint32_t x = (uint32_t)kk << 5;
            uint32_t af[2][4], bf[4][4];        // bf[p] = {n2p:lo,hi, n2p+1:lo,hi}
            ldm_x4(af[0], a0 ^ x);
            ldm_x4(af[1], a1 ^ x);
            ldm_x4(bf[0], b0 ^ x);
            ldm_x4(bf[1], b1 ^ x);
            ldm_x4(bf[2], b2 ^ x);
            ldm_x4(bf[3], b3 ^ x);
#pragma unroll
            for (int mf = 0; mf < 2; mf++)
#pragma unroll
                for (int nf = 0; nf < 8; nf++)
                    mma16(acc[mf][nf], af[mf], &bf[nf >> 1][(nf & 1) * 2]);
        }

        if (kt < KTILES - NSTAGE) {
            if (lane == 0) mbar_arrive(emptyb);  // this warp done reading stage s
            mbar_wait(emptyb, ph);               // all 8 warps done -> stage free
            load_tile(kt + NSTAGE, s);           // refill
            cpa_arrive(fullb);
        }
    }
    __syncthreads();  // all MMAs done before smem reuse

    // ---- epilogue: shfl-pair gate fusion -> smem staging ----
    float* P  = (float*)(smc + SM_PIPE);           // i*g
    float* F  = P + TM * EPS;                      // f
    float* OG = F + TM * EPS;                      // o
    const int odd = tig & 1;

#pragma unroll
    for (int mf = 0; mf < 2; mf++)
#pragma unroll
        for (int nf = 0; nf < 8; nf++) {
            float c0 = acc[mf][nf][0], c1 = acc[mf][nf][1];
            float c2 = acc[mf][nf][2], c3 = acc[mf][nf][3];
            float e0 = __shfl_xor_sync(0xFFFFFFFFu, c0, 1);
            float e1 = __shfl_xor_sync(0xFFFFFFFFu, c1, 1);
            float e2 = __shfl_xor_sync(0xFFFFFFFFu, c2, 1);
            float e3 = __shfl_xor_sync(0xFFFFFFFFu, c3, 1);
            // even lane: row gid,   gates i,f own (c0,c1), g,o from odd (e0,e1)
            // odd lane:  row gid+8, gates g,o own (c2,c3), i,f from even (e2,e3)
            float zi = odd ? e2 : c0;
            float zf = odd ? e3 : c1;
            float zg = odd ? c2 : e0;
            float zo = odd ? c3 : e1;
            int row = wm * 32 + mf * 16 + gid + (odd ? 8 : 0);
            int jl  = wn * 16 + nf * 2 + (tig >> 1);
            float ig = sigm(zi), fg = sigm(zf), gg = tanh_(zg), og = sigm(zo);
            P[row * EPS + jl]  = ig * gg;
            F[row * EPS + jl]  = fg;
            OG[row * EPS + jl] = og;
        }
    __syncthreads();

    // ---- coalesced state update ----
    const bool first = (t == 0);
#pragma unroll
    for (int it = 0; it < (TM * TJ) / NTHR; it++) {
        int idx = it * NTHR + tid;     // 128 rows x 32 j
        int row = idx >> 5, j = idx & 31;
        size_t g = (size_t)(m0 + row) * HDIM + jblk + j;
        float cold = first ? 0.0f : g_c[g];
        float cnew = F[row * EPS + j] * cold + P[row * EPS + j];
        float h = OG[row * EPS + j] * tanh_(cnew);
        g_c[g]  = cnew;
        hist[g] = h;                    // full precision for output
        hdst[g] = __float2half_rn(h);   // fp16 for next GEMM
    }
}

// ---------- final transpose: g_hist[t][n*H+j] -> out[(n*H+j)*L + t] ----------
__global__ void finalize(float* __restrict__ out) {
    const int p = blockIdx.x * 256 + threadIdx.x;
    float v[LSTEPS];
#pragma unroll
    for (int t = 0; t < LSTEPS; t++) v[t] = g_hist[t][p];
    float4* o = (float4*)(out + (size_t)p * LSTEPS);
#pragma unroll
    for (int q = 0; q < LSTEPS / 4; q++)
        o[q] = make_float4(v[4 * q], v[4 * q + 1], v[4 * q + 2], v[4 * q + 3]);
}

extern "C" void kernel_launch(void* const* d_in, const int* in_sizes, int n_in,
                              void* d_out, int out_size) {
    const float* h_in = (const float*)d_in[0];
    const float* W    = (const float*)d_in[1];
    const float* b_ih = (const float*)d_in[2];
    const float* b_hh = (const float*)d_in[3];

    cudaFuncSetAttribute(lstm_step, cudaFuncAttributeMaxDynamicSharedMemorySize, SMEM_TOTAL);

    prep_h<<<NBATCH * HDIM / 4 / 256, 256>>>(h_in);
    prep_w<<<4 * HDIM * HDIM / 4 / 256, 256>>>(W);
    prep_bias<<<16, 256>>>(b_ih, b_hh);

    for (int t = 0; t < LSTEPS; t++) {
        lstm_step<<<dim3(NBATCH / TM, 4 * HDIM / TN), NTHR, SMEM_TOTAL>>>(t);
    }
    finalize<<<NBATCH * HDIM / 256, 256>>>((float*)d_out);
}

// round 10
// speedup vs baseline: 1.1396x; 1.0231x over previous
#include <cuda_runtime.h>
#include <cuda_fp16.h>
#include <cstdint>

// LSTMDecoder on GB300 (sm_103 ptxas -> mma.sync path).
// R10: ONE persistent kernel for all 48 steps. 296 CTAs (2/SM, forced by
// launch_bounds), static tile list (step-major, stride 296), per-(t,x,y)
// readiness flags with release/acquire ordering -> consumers wait only on
// their own column's j-slices, co-resident CTAs desynchronize, and 48
// kernel launches collapse to 1. Per-tile body = R6 (fp16 m16n8k16 +
// ldmatrix.x4, BK=64, 128x128 CTA tile, 32x64 warp tiles, cp.async
// 3-stage, shfl-paired gate fusion). Output via hist + final transpose.

#define HDIM   1024
#define NBATCH 2048
#define LSTEPS 48
#define TM     128
#define TN     128          // 32 j x 4 gates, interleaved j*4+g
#define TJ     32
#define BK     64           // 64 fp16 = 128B rows
#define NSTAGE 3
#define KTILES (HDIM / BK)  // 16
#define NTHR   256
#define NWORK  296          // persistent CTAs = 2/SM x 148 (full residency)
#define TPS    512          // tiles per step (16 x-blocks * 32 y-blocks)

#define SM_BIAS 0
#define SM_PIPE 1024
#define A_BYTES (TM * BK * 2)                       // 16384
#define B_BYTES (TN * BK * 2)                       // 16384
#define STAGE_BYTES (A_BYTES + B_BYTES)             // 32768
#define SMEM_TOTAL (SM_PIPE + NSTAGE * STAGE_BYTES) // 99328 (2 CTAs/SM)

#define EPS 33
#define SWZ(o) ((o) ^ (((o) >> 3) & 0x70))

__device__ __half g_h[2][NBATCH * HDIM];         // fp16 h ping-pong
__device__ float  g_c[NBATCH * HDIM];            // cell state (fp32)
__device__ __half g_Wr[4 * HDIM * HDIM];         // reordered fp16 W: row j*4+g
__device__ float  g_biasr[4 * HDIM];             // reordered bias
__device__ float  g_hist[LSTEPS][NBATCH * HDIM]; // full-precision h history
__device__ int    g_flags[LSTEPS][16][32];       // tile (t,x,y) done

// ---------- helpers ----------
__device__ __forceinline__ uint32_t smem_u32(const void* p) {
    uint32_t a;
    asm("{ .reg .u64 t; cvta.to.shared.u64 t, %1; cvt.u32.u64 %0, t; }" : "=r"(a) : "l"(p));
    return a;
}
__device__ __forceinline__ void cpa16(uint32_t dst, const void* src) {
    asm volatile("cp.async.cg.shared.global [%0], [%1], 16;" :: "r"(dst), "l"(src));
}
#define CP_COMMIT() asm volatile("cp.async.commit_group;" ::: "memory")
#define CP_WAIT(n)  asm volatile("cp.async.wait_group %0;" :: "n"(n) : "memory")

__device__ __forceinline__ int ld_acq(const int* p) {
    int v;
    asm volatile("ld.global.acquire.gpu.b32 %0, [%1];" : "=r"(v) : "l"(p));
    return v;
}
__device__ __forceinline__ void st_rel(int* p, int v) {
    asm volatile("st.global.release.gpu.b32 [%0], %1;" :: "l"(p), "r"(v) : "memory");
}
__device__ __forceinline__ void wait_pair(const int* f) {
    while (ld_acq(f) == 0) { __nanosleep(128); }
    while (ld_acq(f + 1) == 0) { __nanosleep(128); }
}
__device__ __forceinline__ void ldm_x4(uint32_t* r, uint32_t addr) {
    asm volatile("ldmatrix.sync.aligned.m8n8.x4.shared.b16 {%0,%1,%2,%3}, [%4];"
                 : "=r"(r[0]), "=r"(r[1]), "=r"(r[2]), "=r"(r[3]) : "r"(addr));
}
__device__ __forceinline__ void mma16(float* c, const uint32_t* a, const uint32_t* b) {
    asm("mma.sync.aligned.m16n8k16.row.col.f32.f16.f16.f32 "
        "{%0,%1,%2,%3}, {%4,%5,%6,%7}, {%8,%9}, {%0,%1,%2,%3};"
        : "+f"(c[0]), "+f"(c[1]), "+f"(c[2]), "+f"(c[3])
        : "r"(a[0]), "r"(a[1]), "r"(a[2]), "r"(a[3]), "r"(b[0]), "r"(b[1]));
}
__device__ __forceinline__ float sigm(float x) {
    return __fdividef(1.0f, 1.0f + __expf(-x));
}
__device__ __forceinline__ float tanh_(float x) {
    return __fdividef(2.0f, 1.0f + __expf(-2.0f * x)) - 1.0f;
}

// ---------- prep kernels ----------
__global__ void prep_h(const float* __restrict__ h_in) {
    int i = blockIdx.x * 256 + threadIdx.x;
    float4 v = ((const float4*)h_in)[i];
    __half2 lo = __floats2half2_rn(v.x, v.y);
    __half2 hi = __floats2half2_rn(v.z, v.w);
    ((uint2*)g_h[0])[i] = make_uint2(*(uint32_t*)&lo, *(uint32_t*)&hi);
}
__global__ void prep_w(const float* __restrict__ W) {
    int idx = blockIdx.x * 256 + threadIdx.x;
    int rn = idx >> 8, k4 = idx & 255;
    int j = rn >> 2, g = rn & 3;
    float4 v = ((const float4*)W)[(size_t)(g * HDIM + j) * (HDIM / 4) + k4];
    __half2 lo = __floats2half2_rn(v.x, v.y);
    __half2 hi = __floats2half2_rn(v.z, v.w);
    ((uint2*)g_Wr)[(size_t)rn * (HDIM / 4) + k4] =
        make_uint2(*(uint32_t*)&lo, *(uint32_t*)&hi);
}
__global__ void prep_bias(const float* __restrict__ bi, const float* __restrict__ bh) {
    int i = blockIdx.x * 256 + threadIdx.x;
    if (i < 4 * HDIM) {
        int j = i >> 2, g = i & 3;
        g_biasr[i] = bi[g * HDIM + j] + bh[g * HDIM + j];
    }
}
__global__ void reset_flags() {
    int i = blockIdx.x * 256 + threadIdx.x;
    if (i < LSTEPS * 16 * 32) ((int*)g_flags)[i] = 0;
}

// ---------- persistent kernel: all 48 steps ----------
__global__ __launch_bounds__(NTHR, 2)
void lstm_all(void) {
    extern __shared__ char smc[];
    float* sbias = (float*)(smc + SM_BIAS);
    const uint32_t smb = smem_u32(smc);

    const int tid = threadIdx.x;
    const int w = tid >> 5, lane = tid & 31;
    const int gid = lane >> 2, tig = lane & 3;
    const int wm = w & 3, wn = w >> 2;          // 4 x 2 warp grid, 32x64 tiles
    const int rit = lane & 7;
    const int tg  = lane >> 3;

    // ldmatrix lane addressing, relative to stage base; ^ (kk<<5) per k16
    uint32_t ra[2];
#pragma unroll
    for (int mf = 0; mf < 2; mf++) {
        int arow = wm * 32 + mf * 16 + (tg & 1) * 8 + rit;
        ra[mf] = SM_PIPE + (uint32_t)arow * 128 + ((uint32_t)((tg >> 1) ^ rit) << 4);
    }
    uint32_t rb[4];
#pragma unroll
    for (int p = 0; p < 4; p++) {
        int brow = wn * 64 + (2 * p + (tg >> 1)) * 8 + rit;
        rb[p] = SM_PIPE + A_BYTES + (uint32_t)brow * 128 +
                ((uint32_t)((tg & 1) ^ rit) << 4);
    }

#pragma unroll 1
    for (int gidx = blockIdx.x; gidx < LSTEPS * TPS; gidx += NWORK) {
        const int t = gidx >> 9;          // /512
        const int r = gidx & 511;
        const int x = r >> 5;             // m-block 0..15
        const int y = r & 31;             // n-block 0..31
        const int m0 = x * TM;
        const int n0 = y * TN;
        const int jblk = y * TJ;

        const __half* __restrict__ hsrc = g_h[t & 1];
        __half* __restrict__ hdst = g_h[(t + 1) & 1];
        float* __restrict__ hist = g_hist[t];
        const int* fcol = (t > 0) ? &g_flags[t - 1][x][0] : (const int*)0;

        if (tid < TN) sbias[tid] = g_biasr[n0 + tid];

        auto load_tile = [&](int kt, int s) {
            const uint32_t abase = smb + SM_PIPE + s * STAGE_BYTES;
            const uint32_t bbase = abase + A_BYTES;
            const __half* asrc = hsrc + (size_t)m0 * HDIM + kt * BK;
            const __half* bsrc = g_Wr + (size_t)n0 * HDIM + kt * BK;
#pragma unroll
            for (int p = 0; p < 4; p++) {       // A: 128 rows x 128B
                int idx = tid + p * NTHR;
                int row = idx >> 3, ch = idx & 7;
                uint32_t off = (uint32_t)(row * 128 + ch * 16);
                cpa16(abase + SWZ(off), asrc + (size_t)row * HDIM + ch * 8);
            }
#pragma unroll
            for (int p = 0; p < 4; p++) {       // B: 128 rows x 128B
                int idx = tid + p * NTHR;
                int row = idx >> 3, ch = idx & 7;
                uint32_t off = (uint32_t)(row * 128 + ch * 16);
                cpa16(bbase + SWZ(off), bsrc + (size_t)row * HDIM + ch * 8);
            }
        };

        // prologue: tiles 0,1 (wait producer slices for t>0)
        if (t > 0) wait_pair(fcol + 0);
        load_tile(0, 0); CP_COMMIT();
        if (t > 0) wait_pair(fcol + 2);
        load_tile(1, 1); CP_COMMIT();
        __syncthreads();   // sbias visible; prev-tile smem reads done

        // accumulators, bias folded in
        float acc[2][8][4];
#pragma unroll
        for (int mf = 0; mf < 2; mf++)
#pragma unroll
            for (int nf = 0; nf < 8; nf++) {
                int c = wn * 64 + nf * 8 + 2 * tig;
                float b0 = sbias[c], b1 = sbias[c + 1];
                acc[mf][nf][0] = b0; acc[mf][nf][1] = b1;
                acc[mf][nf][2] = b0; acc[mf][nf][3] = b1;
            }

#pragma unroll 1
        for (int kt = 0; kt < KTILES; kt++) {
            const int s = kt % NSTAGE;
            CP_WAIT(1);
            __syncthreads();
            if (kt + 2 < KTILES) {
                if (t > 0) wait_pair(fcol + 2 * (kt + 2));
                load_tile(kt + 2, (kt + 2) % NSTAGE);
            }
            CP_COMMIT();

            const uint32_t sb = smb + (uint32_t)s * STAGE_BYTES;
            const uint32_t a0 = sb + ra[0], a1 = sb + ra[1];
            const uint32_t b0 = sb + rb[0], b1 = sb + rb[1];
            const uint32_t b2 = sb + rb[2], b3 = sb + rb[3];
#pragma unroll
            for (int kk = 0; kk < 4; kk++) {
                const uint32_t xo = (uint32_t)kk << 5;
                uint32_t af[2][4], bf[4][4];
                ldm_x4(af[0], a0 ^ xo);
                ldm_x4(af[1], a1 ^ xo);
                ldm_x4(bf[0], b0 ^ xo);
                ldm_x4(bf[1], b1 ^ xo);
                ldm_x4(bf[2], b2 ^ xo);
                ldm_x4(bf[3], b3 ^ xo);
#pragma unroll
                for (int mf = 0; mf < 2; mf++)
#pragma unroll
                    for (int nf = 0; nf < 8; nf++)
                        mma16(acc[mf][nf], af[mf], &bf[nf >> 1][(nf & 1) * 2]);
            }
        }
        CP_WAIT(0);
        __syncthreads();  // all MMAs done before smem reuse

        // ---- epilogue: shfl-pair gate fusion -> smem staging ----
        float* P  = (float*)(smc + SM_PIPE);
        float* F  = P + TM * EPS;
        float* OG = F + TM * EPS;
        const int odd = tig & 1;

#pragma unroll
        for (int mf = 0; mf < 2; mf++)
#pragma unroll
            for (int nf = 0; nf < 8; nf++) {
                float c0 = acc[mf][nf][0], c1 = acc[mf][nf][1];
                float c2 = acc[mf][nf][2], c3 = acc[mf][nf][3];
                float e0 = __shfl_xor_sync(0xFFFFFFFFu, c0, 1);
                float e1 = __shfl_xor_sync(0xFFFFFFFFu, c1, 1);
                float e2 = __shfl_xor_sync(0xFFFFFFFFu, c2, 1);
                float e3 = __shfl_xor_sync(0xFFFFFFFFu, c3, 1);
                float zi = odd ? e2 : c0;
                float zf = odd ? e3 : c1;
                float zg = odd ? c2 : e0;
                float zo = odd ? c3 : e1;
                int row = wm * 32 + mf * 16 + gid + (odd ? 8 : 0);
                int jl  = wn * 16 + nf * 2 + (tig >> 1);
                float ig = sigm(zi), fg = sigm(zf), gg = tanh_(zg), og = sigm(zo);
                P[row * EPS + jl]  = ig * gg;
                F[row * EPS + jl]  = fg;
                OG[row * EPS + jl] = og;
            }
        __syncthreads();

        // ---- coalesced state update ----
        const bool first = (t == 0);
#pragma unroll
        for (int it = 0; it < (TM * TJ) / NTHR; it++) {
            int idx = it * NTHR + tid;
            int row = idx >> 5, j = idx & 31;
            size_t g = (size_t)(m0 + row) * HDIM + jblk + j;
            float cold = first ? 0.0f : g_c[g];
            float cnew = F[row * EPS + j] * cold + P[row * EPS + j];
            float h = OG[row * EPS + j] * tanh_(cnew);
            g_c[g]  = cnew;
            hist[g] = h;
            hdst[g] = __float2half_rn(h);
        }

        // ---- publish: fence all threads' writes, then release flag ----
        __threadfence();
        __syncthreads();
        if (tid == 0) st_rel(&g_flags[t][x][y], 1);
    }
}

// ---------- final transpose: g_hist[t][n*H+j] -> out[(n*H+j)*L + t] ----------
__global__ void finalize(float* __restrict__ out) {
    const int p = blockIdx.x * 256 + threadIdx.x;
    float v[LSTEPS];
#pragma unroll
    for (int t = 0; t < LSTEPS; t++) v[t] = g_hist[t][p];
    float4* o = (float4*)(out + (size_t)p * LSTEPS);
#pragma unroll
    for (int q = 0; q < LSTEPS / 4; q++)
        o[q] = make_float4(v[4 * q], v[4 * q + 1], v[4 * q + 2], v[4 * q + 3]);
}

extern "C" void kernel_launch(void* const* d_in, const int* in_sizes, int n_in,
                              void* d_out, int out_size) {
    const float* h_in = (const float*)d_in[0];
    const float* W    = (const float*)d_in[1];
    const float* b_ih = (const float*)d_in[2];
    const float* b_hh = (const float*)d_in[3];

    cudaFuncSetAttribute(lstm_all, cudaFuncAttributeMaxDynamicSharedMemorySize, SMEM_TOTAL);

    prep_h<<<NBATCH * HDIM / 4 / 256, 256>>>(h_in);
    prep_w<<<4 * HDIM * HDIM / 4 / 256, 256>>>(W);
    prep_bias<<<16, 256>>>(b_ih, b_hh);
    reset_flags<<<(LSTEPS * 16 * 32 + 255) / 256, 256>>>();

    lstm_all<<<NWORK, NTHR, SMEM_TOTAL>>>();

    finalize<<<NBATCH * HDIM / 256, 256>>>((float*)d_out);
}

// round 11
// speedup vs baseline: 1.1668x; 1.0238x over previous
#include <cuda_runtime.h>
#include <cuda_fp16.h>
#include <cstdint>

// LSTMDecoder on GB300 (sm_103 ptxas -> mma.sync path).
// R11: persistent kernel (R10) + register-neutral fragment software
// pipeline inside each k-tile (A frags double-buffered per k16, B frags
// streamed per n-pair) so LDSM issues ahead of its consuming MMA group,
// letting the LSU/crossbar overlap the tensor pipe at 16 warps/SM.
// Also: h history unified as fp16 g_hs[49] (drops the fp32 hist write and
// halves finalize reads). fp16 m16n8k16 + ldmatrix.x4, BK=64, 128x128 CTA
// tiles, 32x64 warp tiles, 2 CTAs/SM, per-(t,x,y) readiness flags.

#define HDIM   1024
#define NBATCH 2048
#define LSTEPS 48
#define TM     128
#define TN     128          // 32 j x 4 gates, interleaved j*4+g
#define TJ     32
#define BK     64           // 64 fp16 = 128B rows
#define NSTAGE 3
#define KTILES (HDIM / BK)  // 16
#define NTHR   256
#define NWORK  296          // persistent CTAs = 2/SM x 148
#define TPS    512          // tiles per step (16 x * 32 y)

#define SM_BIAS 0
#define SM_PIPE 1024
#define A_BYTES (TM * BK * 2)                       // 16384
#define B_BYTES (TN * BK * 2)                       // 16384
#define STAGE_BYTES (A_BYTES + B_BYTES)             // 32768
#define SMEM_TOTAL (SM_PIPE + NSTAGE * STAGE_BYTES) // 99328 (2 CTAs/SM)

#define EPS 33
#define SWZ(o) ((o) ^ (((o) >> 3) & 0x70))

__device__ __half g_hs[LSTEPS + 1][NBATCH * HDIM]; // fp16 h history (in=0)
__device__ float  g_c[NBATCH * HDIM];              // cell state (fp32)
__device__ __half g_Wr[4 * HDIM * HDIM];           // reordered fp16 W: row j*4+g
__device__ float  g_biasr[4 * HDIM];               // reordered bias
__device__ int    g_flags[LSTEPS][16][32];         // tile (t,x,y) done

// ---------- helpers ----------
__device__ __forceinline__ uint32_t smem_u32(const void* p) {
    uint32_t a;
    asm("{ .reg .u64 t; cvta.to.shared.u64 t, %1; cvt.u32.u64 %0, t; }" : "=r"(a) : "l"(p));
    return a;
}
__device__ __forceinline__ void cpa16(uint32_t dst, const void* src) {
    asm volatile("cp.async.cg.shared.global [%0], [%1], 16;" :: "r"(dst), "l"(src));
}
#define CP_COMMIT() asm volatile("cp.async.commit_group;" ::: "memory")
#define CP_WAIT(n)  asm volatile("cp.async.wait_group %0;" :: "n"(n) : "memory")

__device__ __forceinline__ int ld_acq(const int* p) {
    int v;
    asm volatile("ld.global.acquire.gpu.b32 %0, [%1];" : "=r"(v) : "l"(p));
    return v;
}
__device__ __forceinline__ void st_rel(int* p, int v) {
    asm volatile("st.global.release.gpu.b32 [%0], %1;" :: "l"(p), "r"(v) : "memory");
}
__device__ __forceinline__ void wait_pair(const int* f) {
    while (ld_acq(f) == 0) { __nanosleep(128); }
    while (ld_acq(f + 1) == 0) { __nanosleep(128); }
}
__device__ __forceinline__ void ldm_x4(uint32_t* r, uint32_t addr) {
    asm volatile("ldmatrix.sync.aligned.m8n8.x4.shared.b16 {%0,%1,%2,%3}, [%4];"
                 : "=r"(r[0]), "=r"(r[1]), "=r"(r[2]), "=r"(r[3]) : "r"(addr));
}
__device__ __forceinline__ void mma16(float* c, const uint32_t* a, const uint32_t* b) {
    asm("mma.sync.aligned.m16n8k16.row.col.f32.f16.f16.f32 "
        "{%0,%1,%2,%3}, {%4,%5,%6,%7}, {%8,%9}, {%0,%1,%2,%3};"
        : "+f"(c[0]), "+f"(c[1]), "+f"(c[2]), "+f"(c[3])
        : "r"(a[0]), "r"(a[1]), "r"(a[2]), "r"(a[3]), "r"(b[0]), "r"(b[1]));
}
__device__ __forceinline__ float sigm(float x) {
    return __fdividef(1.0f, 1.0f + __expf(-x));
}
__device__ __forceinline__ float tanh_(float x) {
    return __fdividef(2.0f, 1.0f + __expf(-2.0f * x)) - 1.0f;
}

// ---------- prep kernels ----------
__global__ void prep_h(const float* __restrict__ h_in) {
    int i = blockIdx.x * 256 + threadIdx.x;
    float4 v = ((const float4*)h_in)[i];
    __half2 lo = __floats2half2_rn(v.x, v.y);
    __half2 hi = __floats2half2_rn(v.z, v.w);
    ((uint2*)g_hs[0])[i] = make_uint2(*(uint32_t*)&lo, *(uint32_t*)&hi);
}
__global__ void prep_w(const float* __restrict__ W) {
    int idx = blockIdx.x * 256 + threadIdx.x;
    int rn = idx >> 8, k4 = idx & 255;
    int j = rn >> 2, g = rn & 3;
    float4 v = ((const float4*)W)[(size_t)(g * HDIM + j) * (HDIM / 4) + k4];
    __half2 lo = __floats2half2_rn(v.x, v.y);
    __half2 hi = __floats2half2_rn(v.z, v.w);
    ((uint2*)g_Wr)[(size_t)rn * (HDIM / 4) + k4] =
        make_uint2(*(uint32_t*)&lo, *(uint32_t*)&hi);
}
__global__ void prep_bias(const float* __restrict__ bi, const float* __restrict__ bh) {
    int i = blockIdx.x * 256 + threadIdx.x;
    if (i < 4 * HDIM) {
        int j = i >> 2, g = i & 3;
        g_biasr[i] = bi[g * HDIM + j] + bh[g * HDIM + j];
    }
}
__global__ void reset_flags() {
    int i = blockIdx.x * 256 + threadIdx.x;
    if (i < LSTEPS * 16 * 32) ((int*)g_flags)[i] = 0;
}

// ---------- persistent kernel: all 48 steps ----------
__global__ __launch_bounds__(NTHR, 2)
void lstm_all(void) {
    extern __shared__ char smc[];
    float* sbias = (float*)(smc + SM_BIAS);
    const uint32_t smb = smem_u32(smc);

    const int tid = threadIdx.x;
    const int w = tid >> 5, lane = tid & 31;
    const int gid = lane >> 2, tig = lane & 3;
    const int wm = w & 3, wn = w >> 2;          // 4 x 2 warp grid, 32x64 tiles
    const int rit = lane & 7;
    const int tg  = lane >> 3;

    // ldmatrix lane addressing, relative to stage base; ^ (kk<<5) per k16
    uint32_t ra[2];
#pragma unroll
    for (int mf = 0; mf < 2; mf++) {
        int arow = wm * 32 + mf * 16 + (tg & 1) * 8 + rit;
        ra[mf] = SM_PIPE + (uint32_t)arow * 128 + ((uint32_t)((tg >> 1) ^ rit) << 4);
    }
    uint32_t rb[4];
#pragma unroll
    for (int p = 0; p < 4; p++) {
        int brow = wn * 64 + (2 * p + (tg >> 1)) * 8 + rit;
        rb[p] = SM_PIPE + A_BYTES + (uint32_t)brow * 128 +
                ((uint32_t)((tg & 1) ^ rit) << 4);
    }

#pragma unroll 1
    for (int gidx = blockIdx.x; gidx < LSTEPS * TPS; gidx += NWORK) {
        const int t = gidx >> 9;
        const int r = gidx & 511;
        const int x = r >> 5;             // m-block 0..15
        const int y = r & 31;             // n-block 0..31
        const int m0 = x * TM;
        const int n0 = y * TN;
        const int jblk = y * TJ;

        const __half* __restrict__ hsrc = g_hs[t];
        __half* __restrict__ hdst = g_hs[t + 1];
        const int* fcol = (t > 0) ? &g_flags[t - 1][x][0] : (const int*)0;

        if (tid < TN) sbias[tid] = g_biasr[n0 + tid];

        auto load_tile = [&](int kt, int s) {
            const uint32_t abase = smb + SM_PIPE + s * STAGE_BYTES;
            const uint32_t bbase = abase + A_BYTES;
            const __half* asrc = hsrc + (size_t)m0 * HDIM + kt * BK;
            const __half* bsrc = g_Wr + (size_t)n0 * HDIM + kt * BK;
#pragma unroll
            for (int p = 0; p < 4; p++) {       // A: 128 rows x 128B
                int idx = tid + p * NTHR;
                int row = idx >> 3, ch = idx & 7;
                uint32_t off = (uint32_t)(row * 128 + ch * 16);
                cpa16(abase + SWZ(off), asrc + (size_t)row * HDIM + ch * 8);
            }
#pragma unroll
            for (int p = 0; p < 4; p++) {       // B: 128 rows x 128B
                int idx = tid + p * NTHR;
                int row = idx >> 3, ch = idx & 7;
                uint32_t off = (uint32_t)(row * 128 + ch * 16);
                cpa16(bbase + SWZ(off), bsrc + (size_t)row * HDIM + ch * 8);
            }
        };

        // prologue: tiles 0,1 (wait producer slices for t>0)
        if (t > 0) wait_pair(fcol + 0);
        load_tile(0, 0); CP_COMMIT();
        if (t > 0) wait_pair(fcol + 2);
        load_tile(1, 1); CP_COMMIT();
        __syncthreads();   // sbias visible; prev-tile smem reads done

        // accumulators, bias folded in
        float acc[2][8][4];
#pragma unroll
        for (int mf = 0; mf < 2; mf++)
#pragma unroll
            for (int nf = 0; nf < 8; nf++) {
                int c = wn * 64 + nf * 8 + 2 * tig;
                float b0 = sbias[c], b1 = sbias[c + 1];
                acc[mf][nf][0] = b0; acc[mf][nf][1] = b1;
                acc[mf][nf][2] = b0; acc[mf][nf][3] = b1;
            }

        uint32_t af[2][2][4];   // [buf][mf][frag]
        uint32_t bf[2][4];      // [buf][pair frag]

#pragma unroll 1
        for (int kt = 0; kt < KTILES; kt++) {
            const int s = kt % NSTAGE;
            CP_WAIT(1);
            __syncthreads();
            if (kt + 2 < KTILES) {
                if (t > 0) wait_pair(fcol + 2 * (kt + 2));
                load_tile(kt + 2, (kt + 2) % NSTAGE);
            }
            CP_COMMIT();

            const uint32_t sb = smb + (uint32_t)s * STAGE_BYTES;
            const uint32_t a0 = sb + ra[0], a1 = sb + ra[1];
            const uint32_t bb0 = sb + rb[0], bb1 = sb + rb[1];
            const uint32_t bb2 = sb + rb[2], bb3 = sb + rb[3];

            // prime this tile's pipeline: A(kk0), B(kk0,p0)
            ldm_x4(af[0][0], a0);
            ldm_x4(af[0][1], a1);
            ldm_x4(bf[0], bb0);

#pragma unroll
            for (int kk = 0; kk < 4; kk++) {
                const int ab = kk & 1;
                const uint32_t xc = (uint32_t)kk << 5;
                const uint32_t xn = (uint32_t)((kk + 1) & 3) << 5;
#pragma unroll
                for (int p = 0; p < 4; p++) {
                    const int pb = (kk * 4 + p) & 1;
                    // ---- prefetch next group's fragments ----
                    if (p == 0) {
                        ldm_x4(bf[pb ^ 1], bb1 ^ xc);
                    } else if (p == 1) {
                        ldm_x4(bf[pb ^ 1], bb2 ^ xc);
                    } else if (p == 2) {
                        ldm_x4(bf[pb ^ 1], bb3 ^ xc);
                        if (kk < 3) {
                            ldm_x4(af[ab ^ 1][0], a0 ^ xn);
                            ldm_x4(af[ab ^ 1][1], a1 ^ xn);
                        }
                    } else if (kk < 3) { // p==3
                        ldm_x4(bf[pb ^ 1], bb0 ^ xn);
                    }
                    // ---- 4 MMAs on register-resident fragments ----
                    mma16(acc[0][2 * p],     af[ab][0], &bf[pb][0]);
                    mma16(acc[0][2 * p + 1], af[ab][0], &bf[pb][2]);
                    mma16(acc[1][2 * p],     af[ab][1], &bf[pb][0]);
                    mma16(acc[1][2 * p + 1], af[ab][1], &bf[pb][2]);
                }
            }
        }
        CP_WAIT(0);
        __syncthreads();  // all MMAs done before smem reuse

        // ---- epilogue: shfl-pair gate fusion -> smem staging ----
        float* P  = (float*)(smc + SM_PIPE);
        float* F  = P + TM * EPS;
        float* OG = F + TM * EPS;
        const int odd = tig & 1;

#pragma unroll
        for (int mf = 0; mf < 2; mf++)
#pragma unroll
            for (int nf = 0; nf < 8; nf++) {
                float c0 = acc[mf][nf][0], c1 = acc[mf][nf][1];
                float c2 = acc[mf][nf][2], c3 = acc[mf][nf][3];
                float e0 = __shfl_xor_sync(0xFFFFFFFFu, c0, 1);
                float e1 = __shfl_xor_sync(0xFFFFFFFFu, c1, 1);
                float e2 = __shfl_xor_sync(0xFFFFFFFFu, c2, 1);
                float e3 = __shfl_xor_sync(0xFFFFFFFFu, c3, 1);
                float zi = odd ? e2 : c0;
                float zf = odd ? e3 : c1;
                float zg = odd ? c2 : e0;
                float zo = odd ? c3 : e1;
                int row = wm * 32 + mf * 16 + gid + (odd ? 8 : 0);
                int jl  = wn * 16 + nf * 2 + (tig >> 1);
                float ig = sigm(zi), fg = sigm(zf), gg = tanh_(zg), og = sigm(zo);
                P[row * EPS + jl]  = ig * gg;
                F[row * EPS + jl]  = fg;
                OG[row * EPS + jl] = og;
            }
        __syncthreads();

        // ---- coalesced state update ----
        const bool first = (t == 0);
#pragma unroll
        for (int it = 0; it < (TM * TJ) / NTHR; it++) {
            int idx = it * NTHR + tid;
            int row = idx >> 5, j = idx & 31;
            size_t g = (size_t)(m0 + row) * HDIM + jblk + j;
            float cold = first ? 0.0f : g_c[g];
            float cnew = F[row * EPS + j] * cold + P[row * EPS + j];
            float h = OG[row * EPS + j] * tanh_(cnew);
            g_c[g]  = cnew;
            hdst[g] = __float2half_rn(h);
        }

        // ---- publish ----
        __threadfence();
        __syncthreads();
        if (tid == 0) st_rel(&g_flags[t][x][y], 1);
    }
}

// ---------- finalize: g_hs[t+1][p] -> out[p*L + t] (fp32) ----------
__global__ void finalize(float* __restrict__ out) {
    const int p = blockIdx.x * 256 + threadIdx.x;
    float4* o = (float4*)(out + (size_t)p * LSTEPS);
#pragma unroll
    for (int q = 0; q < LSTEPS / 4; q++) {
        float4 v;
        v.x = __half2float(g_hs[4 * q + 1][p]);
        v.y = __half2float(g_hs[4 * q + 2][p]);
        v.z = __half2float(g_hs[4 * q + 3][p]);
        v.w = __half2float(g_hs[4 * q + 4][p]);
        o[q] = v;
    }
}

extern "C" void kernel_launch(void* const* d_in, const int* in_sizes, int n_in,
                              void* d_out, int out_size) {
    const float* h_in = (const float*)d_in[0];
    const float* W    = (const float*)d_in[1];
    const float* b_ih = (const float*)d_in[2];
    const float* b_hh = (const float*)d_in[3];

    cudaFuncSetAttribute(lstm_all, cudaFuncAttributeMaxDynamicSharedMemorySize, SMEM_TOTAL);

    prep_h<<<NBATCH * HDIM / 4 / 256, 256>>>(h_in);
    prep_w<<<4 * HDIM * HDIM / 4 / 256, 256>>>(W);
    prep_bias<<<16, 256>>>(b_ih, b_hh);
    reset_flags<<<(LSTEPS * 16 * 32 + 255) / 256, 256>>>();

    lstm_all<<<NWORK, NTHR, SMEM_TOTAL>>>();

    finalize<<<NBATCH * HDIM / 256, 256>>>((float*)d_out);
}